// round 2
// baseline (speedup 1.0000x reference)
#include <cuda_runtime.h>

// GINE-conv network:
//   h = emb[x]; h = leaky_relu(gine(h, E1)); h2 = gine(h, E2); out = h2 @ h2.T
// Shapes: N=8192 nodes, E=262144 edges, 128 -> 64 -> 32 dims, out 8192x8192 f32.

#define NN     8192
#define NE     262144
#define EMB    128
#define D1     64
#define D2     32
#define EPSF   1e-9f
#define SLOPEF 0.01f

// Scratch (device globals: no allocation allowed). 16B-aligned for red.v4.
__device__ __align__(16) float g_h[NN * EMB];
__device__ __align__(16) float g_agg1[NN * EMB];
__device__ __align__(16) float g_h1[NN * D1];
__device__ __align__(16) float g_agg2[NN * D1];
__device__ __align__(16) float g_h2[NN * D2];
__device__ int g_x[NN];
__device__ int g_src[NE];
__device__ int g_dst[NE];

__device__ __forceinline__ void fma4(float4& a, float s, const float4& w) {
    a.x = fmaf(s, w.x, a.x);
    a.y = fmaf(s, w.y, a.y);
    a.z = fmaf(s, w.z, a.z);
    a.w = fmaf(s, w.w, a.w);
}

__device__ __forceinline__ void fma2(float2& a, float s, const float2& w) {
    a.x = fmaf(s, w.x, a.x);
    a.y = fmaf(s, w.y, a.y);
}

// ---------------------------------------------------------------------------
// K0: normalize index dtypes. The harness may deliver the reference's int64
// tensors as int32 or as raw int64 words. Detect: if edge_index is int64
// little-endian, every odd 32-bit word is 0 (all values < 8192). Under int32
// data, 32 consecutive odd words all being zero has probability ~(1/8192)^32.
// Deterministic (pure function of input bytes), graph-capturable.
// ---------------------------------------------------------------------------
__global__ void k_convert(const unsigned* __restrict__ xbuf,
                          const unsigned* __restrict__ eibuf) {
    // Cheap per-thread detection: 32 cached broadcast loads.
    unsigned odd_or = 0;
#pragma unroll
    for (int i = 0; i < 32; i++) odd_or |= eibuf[2 * i + 1];
    bool mode64 = (odd_or == 0);

    int t = blockIdx.x * blockDim.x + threadIdx.x;
    if (t < NE) {
        g_src[t] = (int)(mode64 ? eibuf[2 * t]            : eibuf[t]);
        g_dst[t] = (int)(mode64 ? eibuf[2 * (NE + t)]     : eibuf[NE + t]);
    }
    if (t < NN) {
        g_x[t] = (int)(mode64 ? xbuf[2 * t] : xbuf[t]);
    }
}

// ---------------------------------------------------------------------------
// K1: h = emb[x];  agg1 = (1+eps)*h
// ---------------------------------------------------------------------------
__global__ void k_embed(const float4* __restrict__ emb4) {
    int t = blockIdx.x * blockDim.x + threadIdx.x;   // 0 .. NN*32-1
    int node = t >> 5;
    int c    = t & 31;
    float4 v = emb4[g_x[node] * 32 + c];
    ((float4*)g_h)[t] = v;
    float4 a = make_float4(v.x * (1.f + EPSF), v.y * (1.f + EPSF),
                           v.z * (1.f + EPSF), v.w * (1.f + EPSF));
    ((float4*)g_agg1)[t] = a;
}

// ---------------------------------------------------------------------------
// K2: edge pass 1. One warp per edge (grid-stride). Lane owns 4 output cols.
// ee = edge_attr[e] @ E1w + E1b  (16 -> 128, weights live in registers)
// m  = relu(h[src] + ee);  red.v4 into agg1[dst]
// ---------------------------------------------------------------------------
__global__ void __launch_bounds__(256)
k_edge1(const float4* __restrict__ ea4,
        const float4* __restrict__ w4,     // E1w as (16 x 32) float4
        const float4* __restrict__ b4) {   // E1b as 32 float4
    int lane = threadIdx.x & 31;
    int warp = (blockIdx.x * blockDim.x + threadIdx.x) >> 5;
    int nw   = (gridDim.x * blockDim.x) >> 5;

    float4 w[16];
#pragma unroll
    for (int k = 0; k < 16; k++) w[k] = w4[k * 32 + lane];
    float4 bias = b4[lane];

    const float4* h4 = (const float4*)g_h;

    for (int e = warp; e < NE; e += nw) {
        int src = g_src[e];
        int dst = g_dst[e];
        float4 ea0 = ea4[e * 4 + 0];
        float4 ea1 = ea4[e * 4 + 1];
        float4 ea2 = ea4[e * 4 + 2];
        float4 ea3 = ea4[e * 4 + 3];

        float4 acc = bias;
        fma4(acc, ea0.x, w[0]);  fma4(acc, ea0.y, w[1]);
        fma4(acc, ea0.z, w[2]);  fma4(acc, ea0.w, w[3]);
        fma4(acc, ea1.x, w[4]);  fma4(acc, ea1.y, w[5]);
        fma4(acc, ea1.z, w[6]);  fma4(acc, ea1.w, w[7]);
        fma4(acc, ea2.x, w[8]);  fma4(acc, ea2.y, w[9]);
        fma4(acc, ea2.z, w[10]); fma4(acc, ea2.w, w[11]);
        fma4(acc, ea3.x, w[12]); fma4(acc, ea3.y, w[13]);
        fma4(acc, ea3.z, w[14]); fma4(acc, ea3.w, w[15]);

        float4 hv = h4[src * 32 + lane];
        float m0 = fmaxf(hv.x + acc.x, 0.f);
        float m1 = fmaxf(hv.y + acc.y, 0.f);
        float m2 = fmaxf(hv.z + acc.z, 0.f);
        float m3 = fmaxf(hv.w + acc.w, 0.f);

        float* p = g_agg1 + (size_t)dst * EMB + lane * 4;
        asm volatile("red.global.add.v4.f32 [%0], {%1,%2,%3,%4};"
                     :: "l"(p), "f"(m0), "f"(m1), "f"(m2), "f"(m3)
                     : "memory");
    }
}

// ---------------------------------------------------------------------------
// K3: h1 = leaky_relu(agg1 @ W1 + b1);  agg2 = (1+eps)*h1
// ---------------------------------------------------------------------------
__global__ void __launch_bounds__(256)
k_lin1(const float* __restrict__ W1, const float* __restrict__ b1) {
    __shared__ float sW[EMB * D1];     // 32 KB
    __shared__ float srow[4 * EMB];    // 2 KB
    int tid = threadIdx.x;
    for (int i = tid; i < EMB * D1; i += 256) sW[i] = W1[i];
    int node0 = blockIdx.x * 4;
    for (int i = tid; i < 4 * EMB; i += 256) srow[i] = g_agg1[node0 * EMB + i];
    __syncthreads();

    int ln = tid >> 6;     // 0..3
    int c  = tid & 63;
    const float* row = &srow[ln * EMB];
    float acc = b1[c];
#pragma unroll 8
    for (int k = 0; k < EMB; k++) acc = fmaf(row[k], sW[k * D1 + c], acc);
    float v = acc >= 0.f ? acc : SLOPEF * acc;
    int n = node0 + ln;
    g_h1[n * D1 + c]   = v;
    g_agg2[n * D1 + c] = (1.f + EPSF) * v;
}

// ---------------------------------------------------------------------------
// K4: edge pass 2. Warp per edge, lane owns 2 output cols (of 64).
// ee = edge_attr[e] @ E2w + E2b  (16 -> 64); m = relu(h1[src]+ee); red.v2.
// ---------------------------------------------------------------------------
__global__ void __launch_bounds__(256)
k_edge2(const float4* __restrict__ ea4,
        const float2* __restrict__ w2v,    // E2w as (16 x 32) float2
        const float2* __restrict__ b2v) {  // E2b as 32 float2
    int lane = threadIdx.x & 31;
    int warp = (blockIdx.x * blockDim.x + threadIdx.x) >> 5;
    int nw   = (gridDim.x * blockDim.x) >> 5;

    float2 w[16];
#pragma unroll
    for (int k = 0; k < 16; k++) w[k] = w2v[k * 32 + lane];
    float2 bias = b2v[lane];

    const float2* h2v = (const float2*)g_h1;

    for (int e = warp; e < NE; e += nw) {
        int src = g_src[e];
        int dst = g_dst[e];
        float4 ea0 = ea4[e * 4 + 0];
        float4 ea1 = ea4[e * 4 + 1];
        float4 ea2 = ea4[e * 4 + 2];
        float4 ea3 = ea4[e * 4 + 3];

        float2 acc = bias;
        fma2(acc, ea0.x, w[0]);  fma2(acc, ea0.y, w[1]);
        fma2(acc, ea0.z, w[2]);  fma2(acc, ea0.w, w[3]);
        fma2(acc, ea1.x, w[4]);  fma2(acc, ea1.y, w[5]);
        fma2(acc, ea1.z, w[6]);  fma2(acc, ea1.w, w[7]);
        fma2(acc, ea2.x, w[8]);  fma2(acc, ea2.y, w[9]);
        fma2(acc, ea2.z, w[10]); fma2(acc, ea2.w, w[11]);
        fma2(acc, ea3.x, w[12]); fma2(acc, ea3.y, w[13]);
        fma2(acc, ea3.z, w[14]); fma2(acc, ea3.w, w[15]);

        float2 hv = h2v[src * 32 + lane];
        float m0 = fmaxf(hv.x + acc.x, 0.f);
        float m1 = fmaxf(hv.y + acc.y, 0.f);

        float* p = g_agg2 + (size_t)dst * D1 + lane * 2;
        asm volatile("red.global.add.v2.f32 [%0], {%1,%2};"
                     :: "l"(p), "f"(m0), "f"(m1)
                     : "memory");
    }
}

// ---------------------------------------------------------------------------
// K5: h2 = agg2 @ W2 + b2.
// ---------------------------------------------------------------------------
__global__ void __launch_bounds__(256)
k_lin2(const float* __restrict__ W2, const float* __restrict__ b2) {
    __shared__ float sW[D1 * D2];      // 8 KB
    __shared__ float srow[8 * D1];     // 2 KB
    int tid = threadIdx.x;
    for (int i = tid; i < D1 * D2; i += 256) sW[i] = W2[i];
    int node0 = blockIdx.x * 8;
    for (int i = tid; i < 8 * D1; i += 256) srow[i] = g_agg2[node0 * D1 + i];
    __syncthreads();

    int ln = tid >> 5;     // 0..7
    int c  = tid & 31;
    const float* row = &srow[ln * D1];
    float acc = b2[c];
#pragma unroll 8
    for (int k = 0; k < D1; k++) acc = fmaf(row[k], sW[k * D2 + c], acc);
    g_h2[(node0 + ln) * D2 + c] = acc;
}

// ---------------------------------------------------------------------------
// K6: C = h2 @ h2^T  (8192 x 8192, K=32). Symmetric: compute upper-tri tiles
// only; off-diagonal tiles also write the register-transposed mirror tile.
// 128x128 tile, 256 threads, 8x8 micro-tile per thread, K=32 in one shot.
// ---------------------------------------------------------------------------
#define GP 129  // smem row pad (odd stride -> conflict-free transposed access)

__global__ void __launch_bounds__(256)
k_gemm(float* __restrict__ C) {
    int bi = blockIdx.y;
    int bj = blockIdx.x;
    if (bj < bi) return;   // symmetry: only upper triangle

    __shared__ float As[D2][GP];   // [k][row]
    __shared__ float Bs[D2][GP];

    int tid = threadIdx.x;
    for (int i = tid; i < 128 * D2; i += 256) {
        int r = i >> 5;
        int k = i & 31;
        As[k][r] = g_h2[(bi * 128 + r) * D2 + k];
        Bs[k][r] = g_h2[(bj * 128 + r) * D2 + k];
    }
    __syncthreads();

    int tx = tid & 15;     // col group
    int ty = tid >> 4;     // row group
    int i0 = ty * 8;
    int j0 = tx * 8;

    float acc[8][8];
#pragma unroll
    for (int ii = 0; ii < 8; ii++)
#pragma unroll
        for (int jj = 0; jj < 8; jj++) acc[ii][jj] = 0.f;

#pragma unroll 4
    for (int k = 0; k < D2; k++) {
        float a[8], b[8];
#pragma unroll
        for (int ii = 0; ii < 8; ii++) a[ii] = As[k][i0 + ii];
#pragma unroll
        for (int jj = 0; jj < 8; jj++) b[jj] = Bs[k][j0 + jj];
#pragma unroll
        for (int ii = 0; ii < 8; ii++)
#pragma unroll
            for (int jj = 0; jj < 8; jj++)
                acc[ii][jj] = fmaf(a[ii], b[jj], acc[ii][jj]);
    }

    // Write C[bi,bj] tile
    {
        float* Cp = C + (size_t)(bi * 128 + i0) * NN + bj * 128 + j0;
#pragma unroll
        for (int ii = 0; ii < 8; ii++) {
            float4 v0 = make_float4(acc[ii][0], acc[ii][1], acc[ii][2], acc[ii][3]);
            float4 v1 = make_float4(acc[ii][4], acc[ii][5], acc[ii][6], acc[ii][7]);
            ((float4*)(Cp + (size_t)ii * NN))[0] = v0;
            ((float4*)(Cp + (size_t)ii * NN))[1] = v1;
        }
    }
    // Mirror tile C[bj,bi] = transpose
    if (bi != bj) {
        float* Cp = C + (size_t)(bj * 128 + j0) * NN + bi * 128 + i0;
#pragma unroll
        for (int jj = 0; jj < 8; jj++) {
            float4 v0 = make_float4(acc[0][jj], acc[1][jj], acc[2][jj], acc[3][jj]);
            float4 v1 = make_float4(acc[4][jj], acc[5][jj], acc[6][jj], acc[7][jj]);
            ((float4*)(Cp + (size_t)jj * NN))[0] = v0;
            ((float4*)(Cp + (size_t)jj * NN))[1] = v1;
        }
    }
}

// ---------------------------------------------------------------------------
// Launch. Input order (metadata): x, edge_index, edge_attr, emb,
//   W1, b1, E1w, E1b, W2, b2, E2w, E2b.  Output: float32 8192x8192.
// ---------------------------------------------------------------------------
extern "C" void kernel_launch(void* const* d_in, const int* in_sizes, int n_in,
                              void* d_out, int out_size) {
    const unsigned* xbuf  = (const unsigned*)d_in[0];
    const unsigned* eibuf = (const unsigned*)d_in[1];
    const float*    ea    = (const float*)d_in[2];
    const float*    emb   = (const float*)d_in[3];
    const float*    W1    = (const float*)d_in[4];
    const float*    b1    = (const float*)d_in[5];
    const float*    E1w   = (const float*)d_in[6];
    const float*    E1b   = (const float*)d_in[7];
    const float*    W2    = (const float*)d_in[8];
    const float*    b2    = (const float*)d_in[9];
    const float*    E2w   = (const float*)d_in[10];
    const float*    E2b   = (const float*)d_in[11];
    float* out = (float*)d_out;

    k_convert<<<(NE + 255) / 256, 256>>>(xbuf, eibuf);
    k_embed<<<NN * 32 / 256, 256>>>((const float4*)emb);
    k_edge1<<<2048, 256>>>((const float4*)ea,
                           (const float4*)E1w, (const float4*)E1b);
    k_lin1<<<NN / 4, 256>>>(W1, b1);
    k_edge2<<<2048, 256>>>((const float4*)ea,
                           (const float2*)E2w, (const float2*)E2b);
    k_lin2<<<NN / 8, 256>>>(W2, b2);
    dim3 g(NN / 128, NN / 128);
    k_gemm<<<g, 256>>>(out);
}